// round 1
// baseline (speedup 1.0000x reference)
#include <cuda_runtime.h>
#include <cstdint>
#include <cstddef>

// ---------------------------------------------------------------------------
// MultiHeadAttention  (N=4, S=2048, D=1024, H=16, DK=64), fp32 in/out.
// Round 0: unfused TF32 tensor-core pipeline.
//   Q = x Wq^T + bq ; K = x Wk^T + bk ; V = x Wv^T + bv      (gemm_nt)
//   att = softmax(scale * Q_h K_h^T)                          (gemm_nt batched + softmax)
//   Y = att V_h                                               (gemm_nn batched)
//   out = Y Wp^T + bp                                         (gemm_nt)
// ---------------------------------------------------------------------------

namespace {
constexpr int BATCH  = 4;
constexpr int SEQ    = 2048;
constexpr int DMODEL = 1024;
constexpr int NHEAD  = 16;
constexpr int HDIM   = 64;
constexpr int MROWS  = BATCH * SEQ;     // 8192
constexpr float ATT_SCALE = 0.125f;     // 1/sqrt(64)
}

// Scratch (allocation-free rule: __device__ globals).
__device__ float g_Q[(size_t)MROWS * DMODEL];
__device__ float g_K[(size_t)MROWS * DMODEL];
__device__ float g_V[(size_t)MROWS * DMODEL];
__device__ float g_Y[(size_t)MROWS * DMODEL];
__device__ float g_att[(size_t)BATCH * NHEAD * SEQ * SEQ];   // 1 GiB

// ---------------------------------------------------------------------------

__device__ __forceinline__ float to_tf32(float x) {
    float r;
    asm("cvt.rna.tf32.f32 %0, %1;" : "=f"(r) : "f"(x));
    return r;
}

__device__ __forceinline__ void mma_m16n8k8(float c[4], const uint32_t a[4],
                                            const uint32_t b[2]) {
    asm volatile(
        "mma.sync.aligned.m16n8k8.row.col.f32.tf32.tf32.f32 "
        "{%0,%1,%2,%3}, {%4,%5,%6,%7}, {%8,%9}, {%0,%1,%2,%3};\n"
        : "+f"(c[0]), "+f"(c[1]), "+f"(c[2]), "+f"(c[3])
        : "r"(a[0]), "r"(a[1]), "r"(a[2]), "r"(a[3]),
          "r"(b[0]), "r"(b[1]));
}

// ---------------------------------------------------------------------------
// gemm_nt: C[M,N] = scale * (A[M,K] @ B[N,K]^T) + bias
// Batched over blockIdx.z with z -> (n = z/nH, h = z%nH), per-operand
// (outer, inner) batch strides. Tiles: BM=128, BN=128, BK=16; 8 warps (2x4),
// warp tile 64x32 (MT=4 x NT=4 m16n8k8 mmas).
// ---------------------------------------------------------------------------
template <int BM, int BN, int BK>
__global__ __launch_bounds__(256, 2)
void gemm_nt_kernel(const float* __restrict__ A, long aOut, long aIn, int lda,
                    const float* __restrict__ B, long bOut, long bIn, int ldb,
                    float* __restrict__ C, long cOut, long cIn, int ldc,
                    const float* __restrict__ bias, float scale,
                    int Kdim, int nH)
{
    constexpr int MT = 4, NT = 4;
    __shared__ float As[BM][BK + 4];   // stride 20 floats -> conflict-free frag reads
    __shared__ float Bs[BN][BK + 4];

    const int z  = blockIdx.z;
    const int bn = z / nH;
    const int bh = z % nH;
    A += (size_t)bn * aOut + (size_t)bh * aIn;
    B += (size_t)bn * bOut + (size_t)bh * bIn;
    C += (size_t)bn * cOut + (size_t)bh * cIn;

    const int m0 = blockIdx.y * BM;
    const int n0 = blockIdx.x * BN;

    const int tid  = threadIdx.x;
    const int lane = tid & 31;
    const int wid  = tid >> 5;
    const int g    = lane >> 2;       // 0..7
    const int tg   = lane & 3;        // 0..3
    const int wm0  = (wid >> 2) * 64; // 2 warp rows
    const int wn0  = (wid & 3) * 32;  // 4 warp cols

    const int lrow = tid >> 2;        // 0..63
    const int lcol = (tid & 3) * 4;   // 0,4,8,12

    float acc[MT][NT][4];
#pragma unroll
    for (int i = 0; i < MT; i++)
#pragma unroll
        for (int j = 0; j < NT; j++)
#pragma unroll
            for (int r = 0; r < 4; r++) acc[i][j][r] = 0.0f;

    for (int k0 = 0; k0 < Kdim; k0 += BK) {
        __syncthreads();
#pragma unroll
        for (int r = 0; r < BM; r += 64) {
            float4 v = *reinterpret_cast<const float4*>(
                &A[(size_t)(m0 + lrow + r) * lda + k0 + lcol]);
            float4 t = make_float4(to_tf32(v.x), to_tf32(v.y),
                                   to_tf32(v.z), to_tf32(v.w));
            *reinterpret_cast<float4*>(&As[lrow + r][lcol]) = t;
        }
#pragma unroll
        for (int r = 0; r < BN; r += 64) {
            float4 v = *reinterpret_cast<const float4*>(
                &B[(size_t)(n0 + lrow + r) * ldb + k0 + lcol]);
            float4 t = make_float4(to_tf32(v.x), to_tf32(v.y),
                                   to_tf32(v.z), to_tf32(v.w));
            *reinterpret_cast<float4*>(&Bs[lrow + r][lcol]) = t;
        }
        __syncthreads();

#pragma unroll
        for (int kk = 0; kk < BK; kk += 8) {
            uint32_t af[MT][4];
            uint32_t bf[NT][2];
#pragma unroll
            for (int mt = 0; mt < MT; mt++) {
                const int r = wm0 + mt * 16 + g;
                af[mt][0] = __float_as_uint(As[r][kk + tg]);
                af[mt][1] = __float_as_uint(As[r + 8][kk + tg]);
                af[mt][2] = __float_as_uint(As[r][kk + tg + 4]);
                af[mt][3] = __float_as_uint(As[r + 8][kk + tg + 4]);
            }
#pragma unroll
            for (int nt = 0; nt < NT; nt++) {
                const int cidx = wn0 + nt * 8 + g;
                bf[nt][0] = __float_as_uint(Bs[cidx][kk + tg]);
                bf[nt][1] = __float_as_uint(Bs[cidx][kk + tg + 4]);
            }
#pragma unroll
            for (int mt = 0; mt < MT; mt++)
#pragma unroll
                for (int nt = 0; nt < NT; nt++)
                    mma_m16n8k8(acc[mt][nt], af[mt], bf[nt]);
        }
    }

    // Epilogue: C = acc*scale + bias (bias may be null).
#pragma unroll
    for (int mt = 0; mt < MT; mt++) {
#pragma unroll
        for (int nt = 0; nt < NT; nt++) {
            const int row0 = m0 + wm0 + mt * 16 + g;
            const int col  = n0 + wn0 + nt * 8 + 2 * tg;
            float b0 = 0.0f, b1 = 0.0f;
            if (bias) { b0 = bias[col]; b1 = bias[col + 1]; }
            float2 v0 = make_float2(acc[mt][nt][0] * scale + b0,
                                    acc[mt][nt][1] * scale + b1);
            float2 v1 = make_float2(acc[mt][nt][2] * scale + b0,
                                    acc[mt][nt][3] * scale + b1);
            *reinterpret_cast<float2*>(&C[(size_t)row0 * ldc + col])       = v0;
            *reinterpret_cast<float2*>(&C[(size_t)(row0 + 8) * ldc + col]) = v1;
        }
    }
}

// ---------------------------------------------------------------------------
// gemm_nn: C[M,N] = A[M,K] @ B[K,N]   (used for Y = att @ V).
// Tiles: BM=128, BN=64, BK=16; 8 warps (4x2), warp tile 32x32 (MT=2, NT=4).
// ---------------------------------------------------------------------------
template <int BM, int BN, int BK>
__global__ __launch_bounds__(256, 2)
void gemm_nn_kernel(const float* __restrict__ A, long aOut, long aIn, int lda,
                    const float* __restrict__ B, long bOut, long bIn, int ldb,
                    float* __restrict__ C, long cOut, long cIn, int ldc,
                    int Kdim, int nH)
{
    constexpr int MT = 2, NT = 4;
    __shared__ float As[BM][BK + 4];   // [m][k], stride 20
    __shared__ float Bs[BK][BN + 8];   // [k][n], stride 72 -> conflict-free frag reads

    const int z  = blockIdx.z;
    const int bn = z / nH;
    const int bh = z % nH;
    A += (size_t)bn * aOut + (size_t)bh * aIn;
    B += (size_t)bn * bOut + (size_t)bh * bIn;
    C += (size_t)bn * cOut + (size_t)bh * cIn;

    const int m0 = blockIdx.y * BM;
    const int n0 = blockIdx.x * BN;

    const int tid  = threadIdx.x;
    const int lane = tid & 31;
    const int wid  = tid >> 5;
    const int g    = lane >> 2;
    const int tg   = lane & 3;
    const int wm0  = (wid >> 1) * 32;  // 4 warp rows
    const int wn0  = (wid & 1) * 32;   // 2 warp cols

    const int lrow = tid >> 2;         // 0..63  (A tile load)
    const int lcol = (tid & 3) * 4;
    const int krow = tid >> 4;         // 0..15  (B tile load)
    const int c4   = (tid & 15) * 4;   // 0..60

    float acc[MT][NT][4];
#pragma unroll
    for (int i = 0; i < MT; i++)
#pragma unroll
        for (int j = 0; j < NT; j++)
#pragma unroll
            for (int r = 0; r < 4; r++) acc[i][j][r] = 0.0f;

    for (int k0 = 0; k0 < Kdim; k0 += BK) {
        __syncthreads();
#pragma unroll
        for (int r = 0; r < BM; r += 64) {
            float4 v = *reinterpret_cast<const float4*>(
                &A[(size_t)(m0 + lrow + r) * lda + k0 + lcol]);
            float4 t = make_float4(to_tf32(v.x), to_tf32(v.y),
                                   to_tf32(v.z), to_tf32(v.w));
            *reinterpret_cast<float4*>(&As[lrow + r][lcol]) = t;
        }
        {
            float4 v = *reinterpret_cast<const float4*>(
                &B[(size_t)(k0 + krow) * ldb + n0 + c4]);
            float4 t = make_float4(to_tf32(v.x), to_tf32(v.y),
                                   to_tf32(v.z), to_tf32(v.w));
            *reinterpret_cast<float4*>(&Bs[krow][c4]) = t;
        }
        __syncthreads();

#pragma unroll
        for (int kk = 0; kk < BK; kk += 8) {
            uint32_t af[MT][4];
            uint32_t bf[NT][2];
#pragma unroll
            for (int mt = 0; mt < MT; mt++) {
                const int r = wm0 + mt * 16 + g;
                af[mt][0] = __float_as_uint(As[r][kk + tg]);
                af[mt][1] = __float_as_uint(As[r + 8][kk + tg]);
                af[mt][2] = __float_as_uint(As[r][kk + tg + 4]);
                af[mt][3] = __float_as_uint(As[r + 8][kk + tg + 4]);
            }
#pragma unroll
            for (int nt = 0; nt < NT; nt++) {
                const int cidx = wn0 + nt * 8 + g;
                bf[nt][0] = __float_as_uint(Bs[kk + tg][cidx]);
                bf[nt][1] = __float_as_uint(Bs[kk + tg + 4][cidx]);
            }
#pragma unroll
            for (int mt = 0; mt < MT; mt++)
#pragma unroll
                for (int nt = 0; nt < NT; nt++)
                    mma_m16n8k8(acc[mt][nt], af[mt], bf[nt]);
        }
    }

#pragma unroll
    for (int mt = 0; mt < MT; mt++) {
#pragma unroll
        for (int nt = 0; nt < NT; nt++) {
            const int row0 = m0 + wm0 + mt * 16 + g;
            const int col  = n0 + wn0 + nt * 8 + 2 * tg;
            float2 v0 = make_float2(acc[mt][nt][0], acc[mt][nt][1]);
            float2 v1 = make_float2(acc[mt][nt][2], acc[mt][nt][3]);
            *reinterpret_cast<float2*>(&C[(size_t)row0 * ldc + col])       = v0;
            *reinterpret_cast<float2*>(&C[(size_t)(row0 + 8) * ldc + col]) = v1;
        }
    }
}

// ---------------------------------------------------------------------------
// Row softmax over 2048 columns, one block (256 threads) per row, in place.
// ---------------------------------------------------------------------------
__global__ __launch_bounds__(256)
void softmax_rows_2048(float* __restrict__ att)
{
    const int tid  = threadIdx.x;
    const int lane = tid & 31;
    const int wid  = tid >> 5;
    float* p = att + (size_t)blockIdx.x * 2048;

    float4 a = *reinterpret_cast<const float4*>(p + tid * 4);
    float4 b = *reinterpret_cast<const float4*>(p + 1024 + tid * 4);

    __shared__ float red[8];

    // Row max
    float m = fmaxf(fmaxf(fmaxf(a.x, a.y), fmaxf(a.z, a.w)),
                    fmaxf(fmaxf(b.x, b.y), fmaxf(b.z, b.w)));
#pragma unroll
    for (int o = 16; o; o >>= 1) m = fmaxf(m, __shfl_xor_sync(0xffffffffu, m, o));
    if (lane == 0) red[wid] = m;
    __syncthreads();
    m = red[0];
#pragma unroll
    for (int i = 1; i < 8; i++) m = fmaxf(m, red[i]);
    __syncthreads();

    // Exp + row sum
    a.x = __expf(a.x - m); a.y = __expf(a.y - m);
    a.z = __expf(a.z - m); a.w = __expf(a.w - m);
    b.x = __expf(b.x - m); b.y = __expf(b.y - m);
    b.z = __expf(b.z - m); b.w = __expf(b.w - m);
    float s = a.x + a.y + a.z + a.w + b.x + b.y + b.z + b.w;
#pragma unroll
    for (int o = 16; o; o >>= 1) s += __shfl_xor_sync(0xffffffffu, s, o);
    if (lane == 0) red[wid] = s;
    __syncthreads();
    s = red[0] + red[1] + red[2] + red[3] + red[4] + red[5] + red[6] + red[7];

    const float inv = 1.0f / s;
    a.x *= inv; a.y *= inv; a.z *= inv; a.w *= inv;
    b.x *= inv; b.y *= inv; b.z *= inv; b.w *= inv;
    *reinterpret_cast<float4*>(p + tid * 4)        = a;
    *reinterpret_cast<float4*>(p + 1024 + tid * 4) = b;
}

// ---------------------------------------------------------------------------

extern "C" void kernel_launch(void* const* d_in, const int* in_sizes, int n_in,
                              void* d_out, int out_size)
{
    const float* x  = (const float*)d_in[0];
    const float* Wq = (const float*)d_in[1];
    const float* bq = (const float*)d_in[2];
    const float* Wk = (const float*)d_in[3];
    const float* bk = (const float*)d_in[4];
    const float* Wv = (const float*)d_in[5];
    const float* bv = (const float*)d_in[6];
    const float* Wp = (const float*)d_in[7];
    const float* bp = (const float*)d_in[8];
    float* out = (float*)d_out;

    float *Q, *Kp, *V, *Y, *att;
    cudaGetSymbolAddress((void**)&Q,   g_Q);
    cudaGetSymbolAddress((void**)&Kp,  g_K);
    cudaGetSymbolAddress((void**)&V,   g_V);
    cudaGetSymbolAddress((void**)&Y,   g_Y);
    cudaGetSymbolAddress((void**)&att, g_att);

    const dim3 blk(256);

    // --- Q/K/V projections: [8192,1024] = x @ W^T + b ---
    const dim3 gproj(DMODEL / 128, MROWS / 128, 1);
    gemm_nt_kernel<128, 128, 16><<<gproj, blk>>>(
        x, 0, 0, DMODEL, Wq, 0, 0, DMODEL, Q, 0, 0, DMODEL, bq, 1.0f, DMODEL, 1);
    gemm_nt_kernel<128, 128, 16><<<gproj, blk>>>(
        x, 0, 0, DMODEL, Wk, 0, 0, DMODEL, Kp, 0, 0, DMODEL, bk, 1.0f, DMODEL, 1);
    gemm_nt_kernel<128, 128, 16><<<gproj, blk>>>(
        x, 0, 0, DMODEL, Wv, 0, 0, DMODEL, V, 0, 0, DMODEL, bv, 1.0f, DMODEL, 1);

    // --- scores: att[z] = scale * Q_h @ K_h^T,  z = n*H + h ---
    const dim3 gsc(SEQ / 128, SEQ / 128, BATCH * NHEAD);
    gemm_nt_kernel<128, 128, 16><<<gsc, blk>>>(
        Q,  (long)SEQ * DMODEL, HDIM, DMODEL,
        Kp, (long)SEQ * DMODEL, HDIM, DMODEL,
        att, (long)NHEAD * SEQ * SEQ, (long)SEQ * SEQ, SEQ,
        nullptr, ATT_SCALE, HDIM, NHEAD);

    // --- softmax over rows of att ---
    softmax_rows_2048<<<BATCH * NHEAD * SEQ, 256>>>(att);

    // --- Y_h = att @ V_h ---
    const dim3 gpv(HDIM / 64, SEQ / 128, BATCH * NHEAD);
    gemm_nn_kernel<128, 64, 16><<<gpv, blk>>>(
        att, (long)NHEAD * SEQ * SEQ, (long)SEQ * SEQ, SEQ,
        V,   (long)SEQ * DMODEL, HDIM, DMODEL,
        Y,   (long)SEQ * DMODEL, HDIM, DMODEL,
        SEQ, NHEAD);

    // --- output projection: out = Y @ Wp^T + bp ---
    gemm_nt_kernel<128, 128, 16><<<gproj, blk>>>(
        Y, 0, 0, DMODEL, Wp, 0, 0, DMODEL, out, 0, 0, DMODEL, bp, 1.0f, DMODEL, 1);
}

// round 2
// speedup vs baseline: 1.5406x; 1.5406x over previous
#include <cuda_runtime.h>
#include <cstdint>
#include <cstddef>

// ---------------------------------------------------------------------------
// MultiHeadAttention  (N=4, S=2048, D=1024, H=16, DK=64), fp32 in/out.
// Round 1: TF32 projections (unchanged from R0) + fused flash-attention
// kernel (QK^T -> online softmax -> PV in one pass, no 1 GiB att buffer).
// ---------------------------------------------------------------------------

namespace {
constexpr int BATCH  = 4;
constexpr int SEQ    = 2048;
constexpr int DMODEL = 1024;
constexpr int NHEAD  = 16;
constexpr int HDIM   = 64;
constexpr int MROWS  = BATCH * SEQ;     // 8192
constexpr float ATT_SCALE = 0.125f;     // 1/sqrt(64)
}

// Scratch (allocation-free rule: __device__ globals).
__device__ float g_Q[(size_t)MROWS * DMODEL];
__device__ float g_K[(size_t)MROWS * DMODEL];
__device__ float g_V[(size_t)MROWS * DMODEL];
__device__ float g_Y[(size_t)MROWS * DMODEL];

// ---------------------------------------------------------------------------

__device__ __forceinline__ float to_tf32(float x) {
    float r;
    asm("cvt.rna.tf32.f32 %0, %1;" : "=f"(r) : "f"(x));
    return r;
}

__device__ __forceinline__ void mma_m16n8k8(float c[4], const uint32_t a[4],
                                            const uint32_t b[2]) {
    asm volatile(
        "mma.sync.aligned.m16n8k8.row.col.f32.tf32.tf32.f32 "
        "{%0,%1,%2,%3}, {%4,%5,%6,%7}, {%8,%9}, {%0,%1,%2,%3};\n"
        : "+f"(c[0]), "+f"(c[1]), "+f"(c[2]), "+f"(c[3])
        : "r"(a[0]), "r"(a[1]), "r"(a[2]), "r"(a[3]),
          "r"(b[0]), "r"(b[1]));
}

// ---------------------------------------------------------------------------
// gemm_nt: C[M,N] = scale * (A[M,K] @ B[N,K]^T) + bias   (unchanged from R0)
// ---------------------------------------------------------------------------
template <int BM, int BN, int BK>
__global__ __launch_bounds__(256, 2)
void gemm_nt_kernel(const float* __restrict__ A, long aOut, long aIn, int lda,
                    const float* __restrict__ B, long bOut, long bIn, int ldb,
                    float* __restrict__ C, long cOut, long cIn, int ldc,
                    const float* __restrict__ bias, float scale,
                    int Kdim, int nH)
{
    constexpr int MT = 4, NT = 4;
    __shared__ float As[BM][BK + 4];
    __shared__ float Bs[BN][BK + 4];

    const int z  = blockIdx.z;
    const int bn = z / nH;
    const int bh = z % nH;
    A += (size_t)bn * aOut + (size_t)bh * aIn;
    B += (size_t)bn * bOut + (size_t)bh * bIn;
    C += (size_t)bn * cOut + (size_t)bh * cIn;

    const int m0 = blockIdx.y * BM;
    const int n0 = blockIdx.x * BN;

    const int tid  = threadIdx.x;
    const int lane = tid & 31;
    const int wid  = tid >> 5;
    const int g    = lane >> 2;
    const int tg   = lane & 3;
    const int wm0  = (wid >> 2) * 64;
    const int wn0  = (wid & 3) * 32;

    const int lrow = tid >> 2;
    const int lcol = (tid & 3) * 4;

    float acc[MT][NT][4];
#pragma unroll
    for (int i = 0; i < MT; i++)
#pragma unroll
        for (int j = 0; j < NT; j++)
#pragma unroll
            for (int r = 0; r < 4; r++) acc[i][j][r] = 0.0f;

    for (int k0 = 0; k0 < Kdim; k0 += BK) {
        __syncthreads();
#pragma unroll
        for (int r = 0; r < BM; r += 64) {
            float4 v = *reinterpret_cast<const float4*>(
                &A[(size_t)(m0 + lrow + r) * lda + k0 + lcol]);
            float4 t = make_float4(to_tf32(v.x), to_tf32(v.y),
                                   to_tf32(v.z), to_tf32(v.w));
            *reinterpret_cast<float4*>(&As[lrow + r][lcol]) = t;
        }
#pragma unroll
        for (int r = 0; r < BN; r += 64) {
            float4 v = *reinterpret_cast<const float4*>(
                &B[(size_t)(n0 + lrow + r) * ldb + k0 + lcol]);
            float4 t = make_float4(to_tf32(v.x), to_tf32(v.y),
                                   to_tf32(v.z), to_tf32(v.w));
            *reinterpret_cast<float4*>(&Bs[lrow + r][lcol]) = t;
        }
        __syncthreads();

#pragma unroll
        for (int kk = 0; kk < BK; kk += 8) {
            uint32_t af[MT][4];
            uint32_t bf[NT][2];
#pragma unroll
            for (int mt = 0; mt < MT; mt++) {
                const int r = wm0 + mt * 16 + g;
                af[mt][0] = __float_as_uint(As[r][kk + tg]);
                af[mt][1] = __float_as_uint(As[r + 8][kk + tg]);
                af[mt][2] = __float_as_uint(As[r][kk + tg + 4]);
                af[mt][3] = __float_as_uint(As[r + 8][kk + tg + 4]);
            }
#pragma unroll
            for (int nt = 0; nt < NT; nt++) {
                const int cidx = wn0 + nt * 8 + g;
                bf[nt][0] = __float_as_uint(Bs[cidx][kk + tg]);
                bf[nt][1] = __float_as_uint(Bs[cidx][kk + tg + 4]);
            }
#pragma unroll
            for (int mt = 0; mt < MT; mt++)
#pragma unroll
                for (int nt = 0; nt < NT; nt++)
                    mma_m16n8k8(acc[mt][nt], af[mt], bf[nt]);
        }
    }

#pragma unroll
    for (int mt = 0; mt < MT; mt++) {
#pragma unroll
        for (int nt = 0; nt < NT; nt++) {
            const int row0 = m0 + wm0 + mt * 16 + g;
            const int col  = n0 + wn0 + nt * 8 + 2 * tg;
            float b0 = 0.0f, b1 = 0.0f;
            if (bias) { b0 = bias[col]; b1 = bias[col + 1]; }
            float2 v0 = make_float2(acc[mt][nt][0] * scale + b0,
                                    acc[mt][nt][1] * scale + b1);
            float2 v1 = make_float2(acc[mt][nt][2] * scale + b0,
                                    acc[mt][nt][3] * scale + b1);
            *reinterpret_cast<float2*>(&C[(size_t)row0 * ldc + col])       = v0;
            *reinterpret_cast<float2*>(&C[(size_t)(row0 + 8) * ldc + col]) = v1;
        }
    }
}

// ---------------------------------------------------------------------------
// Fused flash attention (tf32 mma).
//   grid = (SEQ/128, BATCH*NHEAD), block = 256 (8 warps).
//   Each CTA: 128 query rows of one (n,h). Loop over 32 KV tiles of 64.
//   Warp w owns q rows [16w, 16w+16): S tile 16x64, online softmax in regs,
//   P round-trips through warp-private SMEM rows (syncwarp only), PV mma
//   accumulates O[16x64] in regs.
// Dynamic SMEM layout (floats):
//   sQ [128][68]  (q rows, pre-scaled, tf32)
//   sP [128][68]  (probabilities, tf32)
//   sK [64][68]   ([kv][dim])
//   sV [64][72]   ([kv][dim], stride 72 -> conflict-free B-frag reads)
// ---------------------------------------------------------------------------
namespace {
constexpr int FA_SQ = 0;
constexpr int FA_SP = 128 * 68;
constexpr int FA_SK = FA_SP + 128 * 68;
constexpr int FA_SV = FA_SK + 64 * 68;
constexpr int FA_SMEM_FLOATS = FA_SV + 64 * 72;   // 26368 floats = 105472 B
}

__global__ __launch_bounds__(256)
void flash_attn_kernel(const float* __restrict__ Q,
                       const float* __restrict__ K,
                       const float* __restrict__ V,
                       float* __restrict__ Y)
{
    extern __shared__ float sm[];
    float* sQ = sm + FA_SQ;
    float* sP = sm + FA_SP;
    float* sK = sm + FA_SK;
    float* sV = sm + FA_SV;

    const int z  = blockIdx.y;          // n*NHEAD + h
    const int bn = z >> 4;
    const int h  = z & 15;

    const size_t rowbase = (size_t)bn * SEQ + (size_t)blockIdx.x * 128;
    const float* Qp = Q + rowbase * DMODEL + h * HDIM;
    const float* Kb = K + (size_t)bn * SEQ * DMODEL + h * HDIM;
    const float* Vb = V + (size_t)bn * SEQ * DMODEL + h * HDIM;
    float*       Yp = Y + rowbase * DMODEL + h * HDIM;

    const int tid  = threadIdx.x;
    const int lane = tid & 31;
    const int wid  = tid >> 5;
    const int g    = lane >> 2;
    const int tg   = lane & 3;
    const int wm   = wid * 16;

    const int lr = tid >> 4;          // 0..15
    const int lc = (tid & 15) * 4;    // 0..60

    // --- stage Q tile (pre-scaled, tf32) ---
#pragma unroll
    for (int r = 0; r < 128; r += 16) {
        float4 v = *reinterpret_cast<const float4*>(
            &Qp[(size_t)(r + lr) * DMODEL + lc]);
        float4 t = make_float4(to_tf32(v.x * ATT_SCALE), to_tf32(v.y * ATT_SCALE),
                               to_tf32(v.z * ATT_SCALE), to_tf32(v.w * ATT_SCALE));
        *reinterpret_cast<float4*>(&sQ[(r + lr) * 68 + lc]) = t;
    }

    float acc_o[8][4];
#pragma unroll
    for (int nt = 0; nt < 8; nt++)
#pragma unroll
        for (int r = 0; r < 4; r++) acc_o[nt][r] = 0.0f;
    float mrow0 = -1e30f, mrow1 = -1e30f;
    float l0 = 0.0f, l1 = 0.0f;

    for (int j = 0; j < SEQ / 64; j++) {
        __syncthreads();   // prev-iter PV reads of sK/sV done; Q staging done (j=0)
        // --- load K/V tile [64][64] (tf32) ---
#pragma unroll
        for (int r = 0; r < 64; r += 16) {
            const size_t grow = (size_t)(j * 64 + r + lr) * DMODEL + lc;
            float4 kv = *reinterpret_cast<const float4*>(&Kb[grow]);
            float4 kt = make_float4(to_tf32(kv.x), to_tf32(kv.y),
                                    to_tf32(kv.z), to_tf32(kv.w));
            *reinterpret_cast<float4*>(&sK[(r + lr) * 68 + lc]) = kt;
            float4 vv = *reinterpret_cast<const float4*>(&Vb[grow]);
            float4 vt = make_float4(to_tf32(vv.x), to_tf32(vv.y),
                                    to_tf32(vv.z), to_tf32(vv.w));
            *reinterpret_cast<float4*>(&sV[(r + lr) * 72 + lc]) = vt;
        }
        __syncthreads();

        // --- S = (Q*scale) @ K^T : 16x64 per warp ---
        float s[8][4];
#pragma unroll
        for (int nt = 0; nt < 8; nt++)
#pragma unroll
            for (int r = 0; r < 4; r++) s[nt][r] = 0.0f;

#pragma unroll
        for (int kk = 0; kk < 8; kk++) {
            uint32_t aq[4];
            aq[0] = __float_as_uint(sQ[(wm + g) * 68 + kk * 8 + tg]);
            aq[1] = __float_as_uint(sQ[(wm + g + 8) * 68 + kk * 8 + tg]);
            aq[2] = __float_as_uint(sQ[(wm + g) * 68 + kk * 8 + tg + 4]);
            aq[3] = __float_as_uint(sQ[(wm + g + 8) * 68 + kk * 8 + tg + 4]);
            uint32_t bf[8][2];
#pragma unroll
            for (int nt = 0; nt < 8; nt++) {
                bf[nt][0] = __float_as_uint(sK[(nt * 8 + g) * 68 + kk * 8 + tg]);
                bf[nt][1] = __float_as_uint(sK[(nt * 8 + g) * 68 + kk * 8 + tg + 4]);
            }
#pragma unroll
            for (int nt = 0; nt < 8; nt++) mma_m16n8k8(s[nt], aq, bf[nt]);
        }

        // --- online softmax (rows g and g+8) ---
        float mx0 = -1e30f, mx1 = -1e30f;
#pragma unroll
        for (int nt = 0; nt < 8; nt++) {
            mx0 = fmaxf(mx0, fmaxf(s[nt][0], s[nt][1]));
            mx1 = fmaxf(mx1, fmaxf(s[nt][2], s[nt][3]));
        }
        mx0 = fmaxf(mx0, __shfl_xor_sync(0xffffffffu, mx0, 1));
        mx0 = fmaxf(mx0, __shfl_xor_sync(0xffffffffu, mx0, 2));
        mx1 = fmaxf(mx1, __shfl_xor_sync(0xffffffffu, mx1, 1));
        mx1 = fmaxf(mx1, __shfl_xor_sync(0xffffffffu, mx1, 2));

        const float nm0 = fmaxf(mrow0, mx0);
        const float nm1 = fmaxf(mrow1, mx1);
        const float al0 = __expf(mrow0 - nm0);
        const float al1 = __expf(mrow1 - nm1);
        mrow0 = nm0; mrow1 = nm1;

        float rs0 = 0.0f, rs1 = 0.0f;
#pragma unroll
        for (int nt = 0; nt < 8; nt++) {
            s[nt][0] = __expf(s[nt][0] - nm0);
            s[nt][1] = __expf(s[nt][1] - nm0);
            s[nt][2] = __expf(s[nt][2] - nm1);
            s[nt][3] = __expf(s[nt][3] - nm1);
            rs0 += s[nt][0] + s[nt][1];
            rs1 += s[nt][2] + s[nt][3];
        }
        rs0 += __shfl_xor_sync(0xffffffffu, rs0, 1);
        rs0 += __shfl_xor_sync(0xffffffffu, rs0, 2);
        rs1 += __shfl_xor_sync(0xffffffffu, rs1, 1);
        rs1 += __shfl_xor_sync(0xffffffffu, rs1, 2);
        l0 = l0 * al0 + rs0;
        l1 = l1 * al1 + rs1;

#pragma unroll
        for (int nt = 0; nt < 8; nt++) {
            acc_o[nt][0] *= al0; acc_o[nt][1] *= al0;
            acc_o[nt][2] *= al1; acc_o[nt][3] *= al1;
        }

        // --- P -> SMEM (warp-private rows, tf32) ---
#pragma unroll
        for (int nt = 0; nt < 8; nt++) {
            sP[(wm + g) * 68 + nt * 8 + 2 * tg]         = to_tf32(s[nt][0]);
            sP[(wm + g) * 68 + nt * 8 + 2 * tg + 1]     = to_tf32(s[nt][1]);
            sP[(wm + g + 8) * 68 + nt * 8 + 2 * tg]     = to_tf32(s[nt][2]);
            sP[(wm + g + 8) * 68 + nt * 8 + 2 * tg + 1] = to_tf32(s[nt][3]);
        }
        __syncwarp();

        // --- O += P @ V : 16x64 per warp, k = 64 ---
#pragma unroll
        for (int kk = 0; kk < 8; kk++) {
            uint32_t af[4];
            af[0] = __float_as_uint(sP[(wm + g) * 68 + kk * 8 + tg]);
            af[1] = __float_as_uint(sP[(wm + g + 8) * 68 + kk * 8 + tg]);
            af[2] = __float_as_uint(sP[(wm + g) * 68 + kk * 8 + tg + 4]);
            af[3] = __float_as_uint(sP[(wm + g + 8) * 68 + kk * 8 + tg + 4]);
            uint32_t bf[8][2];
#pragma unroll
            for (int nt = 0; nt < 8; nt++) {
                bf[nt][0] = __float_as_uint(sV[(kk * 8 + tg) * 72 + nt * 8 + g]);
                bf[nt][1] = __float_as_uint(sV[(kk * 8 + tg + 4) * 72 + nt * 8 + g]);
            }
#pragma unroll
            for (int nt = 0; nt < 8; nt++) mma_m16n8k8(acc_o[nt], af, bf[nt]);
        }
    }

    // --- epilogue: O / l -> Y ---
    const float inv0 = 1.0f / l0;
    const float inv1 = 1.0f / l1;
#pragma unroll
    for (int nt = 0; nt < 8; nt++) {
        float2 v0 = make_float2(acc_o[nt][0] * inv0, acc_o[nt][1] * inv0);
        float2 v1 = make_float2(acc_o[nt][2] * inv1, acc_o[nt][3] * inv1);
        *reinterpret_cast<float2*>(&Yp[(size_t)(wm + g) * DMODEL + nt * 8 + 2 * tg])     = v0;
        *reinterpret_cast<float2*>(&Yp[(size_t)(wm + g + 8) * DMODEL + nt * 8 + 2 * tg]) = v1;
    }
}

// ---------------------------------------------------------------------------

extern "C" void kernel_launch(void* const* d_in, const int* in_sizes, int n_in,
                              void* d_out, int out_size)
{
    const float* x  = (const float*)d_in[0];
    const float* Wq = (const float*)d_in[1];
    const float* bq = (const float*)d_in[2];
    const float* Wk = (const float*)d_in[3];
    const float* bk = (const float*)d_in[4];
    const float* Wv = (const float*)d_in[5];
    const float* bv = (const float*)d_in[6];
    const float* Wp = (const float*)d_in[7];
    const float* bp = (const float*)d_in[8];
    float* out = (float*)d_out;

    float *Q, *Kp, *V, *Y;
    cudaGetSymbolAddress((void**)&Q,  g_Q);
    cudaGetSymbolAddress((void**)&Kp, g_K);
    cudaGetSymbolAddress((void**)&V,  g_V);
    cudaGetSymbolAddress((void**)&Y,  g_Y);

    const dim3 blk(256);

    // --- Q/K/V projections ---
    const dim3 gproj(DMODEL / 128, MROWS / 128, 1);
    gemm_nt_kernel<128, 128, 16><<<gproj, blk>>>(
        x, 0, 0, DMODEL, Wq, 0, 0, DMODEL, Q, 0, 0, DMODEL, bq, 1.0f, DMODEL, 1);
    gemm_nt_kernel<128, 128, 16><<<gproj, blk>>>(
        x, 0, 0, DMODEL, Wk, 0, 0, DMODEL, Kp, 0, 0, DMODEL, bk, 1.0f, DMODEL, 1);
    gemm_nt_kernel<128, 128, 16><<<gproj, blk>>>(
        x, 0, 0, DMODEL, Wv, 0, 0, DMODEL, V, 0, 0, DMODEL, bv, 1.0f, DMODEL, 1);

    // --- fused attention ---
    constexpr int FA_SMEM_BYTES = FA_SMEM_FLOATS * 4;
    cudaFuncSetAttribute(flash_attn_kernel,
                         cudaFuncAttributeMaxDynamicSharedMemorySize,
                         FA_SMEM_BYTES);
    const dim3 gfa(SEQ / 128, BATCH * NHEAD);
    flash_attn_kernel<<<gfa, blk, FA_SMEM_BYTES>>>(Q, Kp, V, Y);

    // --- output projection ---
    gemm_nt_kernel<128, 128, 16><<<gproj, blk>>>(
        Y, 0, 0, DMODEL, Wp, 0, 0, DMODEL, out, 0, 0, DMODEL, bp, 1.0f, DMODEL, 1);
}

// round 3
// speedup vs baseline: 1.5417x; 1.0007x over previous
#include <cuda_runtime.h>
#include <cstdint>
#include <cstddef>

// ---------------------------------------------------------------------------
// MultiHeadAttention  (N=4, S=2048, D=1024, H=16, DK=64), fp32 in/out.
// Round 1: TF32 projections (unchanged from R0) + fused flash-attention
// kernel (QK^T -> online softmax -> PV in one pass, no 1 GiB att buffer).
// ---------------------------------------------------------------------------

namespace {
constexpr int BATCH  = 4;
constexpr int SEQ    = 2048;
constexpr int DMODEL = 1024;
constexpr int NHEAD  = 16;
constexpr int HDIM   = 64;
constexpr int MROWS  = BATCH * SEQ;     // 8192
constexpr float ATT_SCALE = 0.125f;     // 1/sqrt(64)
}

// Scratch (allocation-free rule: __device__ globals).
__device__ float g_Q[(size_t)MROWS * DMODEL];
__device__ float g_K[(size_t)MROWS * DMODEL];
__device__ float g_V[(size_t)MROWS * DMODEL];
__device__ float g_Y[(size_t)MROWS * DMODEL];

// ---------------------------------------------------------------------------

__device__ __forceinline__ float to_tf32(float x) {
    float r;
    asm("cvt.rna.tf32.f32 %0, %1;" : "=f"(r) : "f"(x));
    return r;
}

__device__ __forceinline__ void mma_m16n8k8(float c[4], const uint32_t a[4],
                                            const uint32_t b[2]) {
    asm volatile(
        "mma.sync.aligned.m16n8k8.row.col.f32.tf32.tf32.f32 "
        "{%0,%1,%2,%3}, {%4,%5,%6,%7}, {%8,%9}, {%0,%1,%2,%3};\n"
        : "+f"(c[0]), "+f"(c[1]), "+f"(c[2]), "+f"(c[3])
        : "r"(a[0]), "r"(a[1]), "r"(a[2]), "r"(a[3]),
          "r"(b[0]), "r"(b[1]));
}

// ---------------------------------------------------------------------------
// gemm_nt: C[M,N] = scale * (A[M,K] @ B[N,K]^T) + bias   (unchanged from R0)
// ---------------------------------------------------------------------------
template <int BM, int BN, int BK>
__global__ __launch_bounds__(256, 2)
void gemm_nt_kernel(const float* __restrict__ A, long aOut, long aIn, int lda,
                    const float* __restrict__ B, long bOut, long bIn, int ldb,
                    float* __restrict__ C, long cOut, long cIn, int ldc,
                    const float* __restrict__ bias, float scale,
                    int Kdim, int nH)
{
    constexpr int MT = 4, NT = 4;
    __shared__ float As[BM][BK + 4];
    __shared__ float Bs[BN][BK + 4];

    const int z  = blockIdx.z;
    const int bn = z / nH;
    const int bh = z % nH;
    A += (size_t)bn * aOut + (size_t)bh * aIn;
    B += (size_t)bn * bOut + (size_t)bh * bIn;
    C += (size_t)bn * cOut + (size_t)bh * cIn;

    const int m0 = blockIdx.y * BM;
    const int n0 = blockIdx.x * BN;

    const int tid  = threadIdx.x;
    const int lane = tid & 31;
    const int wid  = tid >> 5;
    const int g    = lane >> 2;
    const int tg   = lane & 3;
    const int wm0  = (wid >> 2) * 64;
    const int wn0  = (wid & 3) * 32;

    const int lrow = tid >> 2;
    const int lcol = (tid & 3) * 4;

    float acc[MT][NT][4];
#pragma unroll
    for (int i = 0; i < MT; i++)
#pragma unroll
        for (int j = 0; j < NT; j++)
#pragma unroll
            for (int r = 0; r < 4; r++) acc[i][j][r] = 0.0f;

    for (int k0 = 0; k0 < Kdim; k0 += BK) {
        __syncthreads();
#pragma unroll
        for (int r = 0; r < BM; r += 64) {
            float4 v = *reinterpret_cast<const float4*>(
                &A[(size_t)(m0 + lrow + r) * lda + k0 + lcol]);
            float4 t = make_float4(to_tf32(v.x), to_tf32(v.y),
                                   to_tf32(v.z), to_tf32(v.w));
            *reinterpret_cast<float4*>(&As[lrow + r][lcol]) = t;
        }
#pragma unroll
        for (int r = 0; r < BN; r += 64) {
            float4 v = *reinterpret_cast<const float4*>(
                &B[(size_t)(n0 + lrow + r) * ldb + k0 + lcol]);
            float4 t = make_float4(to_tf32(v.x), to_tf32(v.y),
                                   to_tf32(v.z), to_tf32(v.w));
            *reinterpret_cast<float4*>(&Bs[lrow + r][lcol]) = t;
        }
        __syncthreads();

#pragma unroll
        for (int kk = 0; kk < BK; kk += 8) {
            uint32_t af[MT][4];
            uint32_t bf[NT][2];
#pragma unroll
            for (int mt = 0; mt < MT; mt++) {
                const int r = wm0 + mt * 16 + g;
                af[mt][0] = __float_as_uint(As[r][kk + tg]);
                af[mt][1] = __float_as_uint(As[r + 8][kk + tg]);
                af[mt][2] = __float_as_uint(As[r][kk + tg + 4]);
                af[mt][3] = __float_as_uint(As[r + 8][kk + tg + 4]);
            }
#pragma unroll
            for (int nt = 0; nt < NT; nt++) {
                const int cidx = wn0 + nt * 8 + g;
                bf[nt][0] = __float_as_uint(Bs[cidx][kk + tg]);
                bf[nt][1] = __float_as_uint(Bs[cidx][kk + tg + 4]);
            }
#pragma unroll
            for (int mt = 0; mt < MT; mt++)
#pragma unroll
                for (int nt = 0; nt < NT; nt++)
                    mma_m16n8k8(acc[mt][nt], af[mt], bf[nt]);
        }
    }

#pragma unroll
    for (int mt = 0; mt < MT; mt++) {
#pragma unroll
        for (int nt = 0; nt < NT; nt++) {
            const int row0 = m0 + wm0 + mt * 16 + g;
            const int col  = n0 + wn0 + nt * 8 + 2 * tg;
            float b0 = 0.0f, b1 = 0.0f;
            if (bias) { b0 = bias[col]; b1 = bias[col + 1]; }
            float2 v0 = make_float2(acc[mt][nt][0] * scale + b0,
                                    acc[mt][nt][1] * scale + b1);
            float2 v1 = make_float2(acc[mt][nt][2] * scale + b0,
                                    acc[mt][nt][3] * scale + b1);
            *reinterpret_cast<float2*>(&C[(size_t)row0 * ldc + col])       = v0;
            *reinterpret_cast<float2*>(&C[(size_t)(row0 + 8) * ldc + col]) = v1;
        }
    }
}

// ---------------------------------------------------------------------------
// Fused flash attention (tf32 mma).
//   grid = (SEQ/128, BATCH*NHEAD), block = 256 (8 warps).
//   Each CTA: 128 query rows of one (n,h). Loop over 32 KV tiles of 64.
//   Warp w owns q rows [16w, 16w+16): S tile 16x64, online softmax in regs,
//   P round-trips through warp-private SMEM rows (syncwarp only), PV mma
//   accumulates O[16x64] in regs.
// Dynamic SMEM layout (floats):
//   sQ [128][68]  (q rows, pre-scaled, tf32)
//   sP [128][68]  (probabilities, tf32)
//   sK [64][68]   ([kv][dim])
//   sV [64][72]   ([kv][dim], stride 72 -> conflict-free B-frag reads)
// ---------------------------------------------------------------------------
namespace {
constexpr int FA_SQ = 0;
constexpr int FA_SP = 128 * 68;
constexpr int FA_SK = FA_SP + 128 * 68;
constexpr int FA_SV = FA_SK + 64 * 68;
constexpr int FA_SMEM_FLOATS = FA_SV + 64 * 72;   // 26368 floats = 105472 B
}

__global__ __launch_bounds__(256)
void flash_attn_kernel(const float* __restrict__ Q,
                       const float* __restrict__ K,
                       const float* __restrict__ V,
                       float* __restrict__ Y)
{
    extern __shared__ float sm[];
    float* sQ = sm + FA_SQ;
    float* sP = sm + FA_SP;
    float* sK = sm + FA_SK;
    float* sV = sm + FA_SV;

    const int z  = blockIdx.y;          // n*NHEAD + h
    const int bn = z >> 4;
    const int h  = z & 15;

    const size_t rowbase = (size_t)bn * SEQ + (size_t)blockIdx.x * 128;
    const float* Qp = Q + rowbase * DMODEL + h * HDIM;
    const float* Kb = K + (size_t)bn * SEQ * DMODEL + h * HDIM;
    const float* Vb = V + (size_t)bn * SEQ * DMODEL + h * HDIM;
    float*       Yp = Y + rowbase * DMODEL + h * HDIM;

    const int tid  = threadIdx.x;
    const int lane = tid & 31;
    const int wid  = tid >> 5;
    const int g    = lane >> 2;
    const int tg   = lane & 3;
    const int wm   = wid * 16;

    const int lr = tid >> 4;          // 0..15
    const int lc = (tid & 15) * 4;    // 0..60

    // --- stage Q tile (pre-scaled, tf32) ---
#pragma unroll
    for (int r = 0; r < 128; r += 16) {
        float4 v = *reinterpret_cast<const float4*>(
            &Qp[(size_t)(r + lr) * DMODEL + lc]);
        float4 t = make_float4(to_tf32(v.x * ATT_SCALE), to_tf32(v.y * ATT_SCALE),
                               to_tf32(v.z * ATT_SCALE), to_tf32(v.w * ATT_SCALE));
        *reinterpret_cast<float4*>(&sQ[(r + lr) * 68 + lc]) = t;
    }

    float acc_o[8][4];
#pragma unroll
    for (int nt = 0; nt < 8; nt++)
#pragma unroll
        for (int r = 0; r < 4; r++) acc_o[nt][r] = 0.0f;
    float mrow0 = -1e30f, mrow1 = -1e30f;
    float l0 = 0.0f, l1 = 0.0f;

    for (int j = 0; j < SEQ / 64; j++) {
        __syncthreads();   // prev-iter PV reads of sK/sV done; Q staging done (j=0)
        // --- load K/V tile [64][64] (tf32) ---
#pragma unroll
        for (int r = 0; r < 64; r += 16) {
            const size_t grow = (size_t)(j * 64 + r + lr) * DMODEL + lc;
            float4 kv = *reinterpret_cast<const float4*>(&Kb[grow]);
            float4 kt = make_float4(to_tf32(kv.x), to_tf32(kv.y),
                                    to_tf32(kv.z), to_tf32(kv.w));
            *reinterpret_cast<float4*>(&sK[(r + lr) * 68 + lc]) = kt;
            float4 vv = *reinterpret_cast<const float4*>(&Vb[grow]);
            float4 vt = make_float4(to_tf32(vv.x), to_tf32(vv.y),
                                    to_tf32(vv.z), to_tf32(vv.w));
            *reinterpret_cast<float4*>(&sV[(r + lr) * 72 + lc]) = vt;
        }
        __syncthreads();

        // --- S = (Q*scale) @ K^T : 16x64 per warp ---
        float s[8][4];
#pragma unroll
        for (int nt = 0; nt < 8; nt++)
#pragma unroll
            for (int r = 0; r < 4; r++) s[nt][r] = 0.0f;

#pragma unroll
        for (int kk = 0; kk < 8; kk++) {
            uint32_t aq[4];
            aq[0] = __float_as_uint(sQ[(wm + g) * 68 + kk * 8 + tg]);
            aq[1] = __float_as_uint(sQ[(wm + g + 8) * 68 + kk * 8 + tg]);
            aq[2] = __float_as_uint(sQ[(wm + g) * 68 + kk * 8 + tg + 4]);
            aq[3] = __float_as_uint(sQ[(wm + g + 8) * 68 + kk * 8 + tg + 4]);
            uint32_t bf[8][2];
#pragma unroll
            for (int nt = 0; nt < 8; nt++) {
                bf[nt][0] = __float_as_uint(sK[(nt * 8 + g) * 68 + kk * 8 + tg]);
                bf[nt][1] = __float_as_uint(sK[(nt * 8 + g) * 68 + kk * 8 + tg + 4]);
            }
#pragma unroll
            for (int nt = 0; nt < 8; nt++) mma_m16n8k8(s[nt], aq, bf[nt]);
        }

        // --- online softmax (rows g and g+8) ---
        float mx0 = -1e30f, mx1 = -1e30f;
#pragma unroll
        for (int nt = 0; nt < 8; nt++) {
            mx0 = fmaxf(mx0, fmaxf(s[nt][0], s[nt][1]));
            mx1 = fmaxf(mx1, fmaxf(s[nt][2], s[nt][3]));
        }
        mx0 = fmaxf(mx0, __shfl_xor_sync(0xffffffffu, mx0, 1));
        mx0 = fmaxf(mx0, __shfl_xor_sync(0xffffffffu, mx0, 2));
        mx1 = fmaxf(mx1, __shfl_xor_sync(0xffffffffu, mx1, 1));
        mx1 = fmaxf(mx1, __shfl_xor_sync(0xffffffffu, mx1, 2));

        const float nm0 = fmaxf(mrow0, mx0);
        const float nm1 = fmaxf(mrow1, mx1);
        const float al0 = __expf(mrow0 - nm0);
        const float al1 = __expf(mrow1 - nm1);
        mrow0 = nm0; mrow1 = nm1;

        float rs0 = 0.0f, rs1 = 0.0f;
#pragma unroll
        for (int nt = 0; nt < 8; nt++) {
            s[nt][0] = __expf(s[nt][0] - nm0);
            s[nt][1] = __expf(s[nt][1] - nm0);
            s[nt][2] = __expf(s[nt][2] - nm1);
            s[nt][3] = __expf(s[nt][3] - nm1);
            rs0 += s[nt][0] + s[nt][1];
            rs1 += s[nt][2] + s[nt][3];
        }
        rs0 += __shfl_xor_sync(0xffffffffu, rs0, 1);
        rs0 += __shfl_xor_sync(0xffffffffu, rs0, 2);
        rs1 += __shfl_xor_sync(0xffffffffu, rs1, 1);
        rs1 += __shfl_xor_sync(0xffffffffu, rs1, 2);
        l0 = l0 * al0 + rs0;
        l1 = l1 * al1 + rs1;

#pragma unroll
        for (int nt = 0; nt < 8; nt++) {
            acc_o[nt][0] *= al0; acc_o[nt][1] *= al0;
            acc_o[nt][2] *= al1; acc_o[nt][3] *= al1;
        }

        // --- P -> SMEM (warp-private rows, tf32) ---
#pragma unroll
        for (int nt = 0; nt < 8; nt++) {
            sP[(wm + g) * 68 + nt * 8 + 2 * tg]         = to_tf32(s[nt][0]);
            sP[(wm + g) * 68 + nt * 8 + 2 * tg + 1]     = to_tf32(s[nt][1]);
            sP[(wm + g + 8) * 68 + nt * 8 + 2 * tg]     = to_tf32(s[nt][2]);
            sP[(wm + g + 8) * 68 + nt * 8 + 2 * tg + 1] = to_tf32(s[nt][3]);
        }
        __syncwarp();

        // --- O += P @ V : 16x64 per warp, k = 64 ---
#pragma unroll
        for (int kk = 0; kk < 8; kk++) {
            uint32_t af[4];
            af[0] = __float_as_uint(sP[(wm + g) * 68 + kk * 8 + tg]);
            af[1] = __float_as_uint(sP[(wm + g + 8) * 68 + kk * 8 + tg]);
            af[2] = __float_as_uint(sP[(wm + g) * 68 + kk * 8 + tg + 4]);
            af[3] = __float_as_uint(sP[(wm + g + 8) * 68 + kk * 8 + tg + 4]);
            uint32_t bf[8][2];
#pragma unroll
            for (int nt = 0; nt < 8; nt++) {
                bf[nt][0] = __float_as_uint(sV[(kk * 8 + tg) * 72 + nt * 8 + g]);
                bf[nt][1] = __float_as_uint(sV[(kk * 8 + tg + 4) * 72 + nt * 8 + g]);
            }
#pragma unroll
            for (int nt = 0; nt < 8; nt++) mma_m16n8k8(acc_o[nt], af, bf[nt]);
        }
    }

    // --- epilogue: O / l -> Y ---
    const float inv0 = 1.0f / l0;
    const float inv1 = 1.0f / l1;
#pragma unroll
    for (int nt = 0; nt < 8; nt++) {
        float2 v0 = make_float2(acc_o[nt][0] * inv0, acc_o[nt][1] * inv0);
        float2 v1 = make_float2(acc_o[nt][2] * inv1, acc_o[nt][3] * inv1);
        *reinterpret_cast<float2*>(&Yp[(size_t)(wm + g) * DMODEL + nt * 8 + 2 * tg])     = v0;
        *reinterpret_cast<float2*>(&Yp[(size_t)(wm + g + 8) * DMODEL + nt * 8 + 2 * tg]) = v1;
    }
}

// ---------------------------------------------------------------------------

extern "C" void kernel_launch(void* const* d_in, const int* in_sizes, int n_in,
                              void* d_out, int out_size)
{
    const float* x  = (const float*)d_in[0];
    const float* Wq = (const float*)d_in[1];
    const float* bq = (const float*)d_in[2];
    const float* Wk = (const float*)d_in[3];
    const float* bk = (const float*)d_in[4];
    const float* Wv = (const float*)d_in[5];
    const float* bv = (const float*)d_in[6];
    const float* Wp = (const float*)d_in[7];
    const float* bp = (const float*)d_in[8];
    float* out = (float*)d_out;

    float *Q, *Kp, *V, *Y;
    cudaGetSymbolAddress((void**)&Q,  g_Q);
    cudaGetSymbolAddress((void**)&Kp, g_K);
    cudaGetSymbolAddress((void**)&V,  g_V);
    cudaGetSymbolAddress((void**)&Y,  g_Y);

    const dim3 blk(256);

    // --- Q/K/V projections ---
    const dim3 gproj(DMODEL / 128, MROWS / 128, 1);
    gemm_nt_kernel<128, 128, 16><<<gproj, blk>>>(
        x, 0, 0, DMODEL, Wq, 0, 0, DMODEL, Q, 0, 0, DMODEL, bq, 1.0f, DMODEL, 1);
    gemm_nt_kernel<128, 128, 16><<<gproj, blk>>>(
        x, 0, 0, DMODEL, Wk, 0, 0, DMODEL, Kp, 0, 0, DMODEL, bk, 1.0f, DMODEL, 1);
    gemm_nt_kernel<128, 128, 16><<<gproj, blk>>>(
        x, 0, 0, DMODEL, Wv, 0, 0, DMODEL, V, 0, 0, DMODEL, bv, 1.0f, DMODEL, 1);

    // --- fused attention ---
    constexpr int FA_SMEM_BYTES = FA_SMEM_FLOATS * 4;
    cudaFuncSetAttribute(flash_attn_kernel,
                         cudaFuncAttributeMaxDynamicSharedMemorySize,
                         FA_SMEM_BYTES);
    const dim3 gfa(SEQ / 128, BATCH * NHEAD);
    flash_attn_kernel<<<gfa, blk, FA_SMEM_BYTES>>>(Q, Kp, V, Y);

    // --- output projection ---
    gemm_nt_kernel<128, 128, 16><<<gproj, blk>>>(
        Y, 0, 0, DMODEL, Wp, 0, 0, DMODEL, out, 0, 0, DMODEL, bp, 1.0f, DMODEL, 1);
}

// round 5
// speedup vs baseline: 1.9493x; 1.2644x over previous
#include <cuda_runtime.h>
#include <cstdint>
#include <cstddef>

namespace {
constexpr int BATCH  = 4;
constexpr int SEQ    = 2048;
constexpr int DMODEL = 1024;
constexpr int HDIM   = 64;
constexpr int MROWS  = BATCH * SEQ;     // 8192
constexpr float ATT_SCALE = 0.125f;

constexpr int FP_P = 0;                 // sP [128][68]
constexpr int FP_K = 128 * 68;          // sK [64][68]
constexpr int FP_V = FP_K + 64 * 68;    // sV [64][72]
constexpr int FLASH_SMEM_FLOATS = FP_V + 64 * 72;   // 17664 floats = 70656 B
}

__device__ float g_Q[(size_t)MROWS * DMODEL];
__device__ float g_K[(size_t)MROWS * DMODEL];
__device__ float g_V[(size_t)MROWS * DMODEL];
__device__ float g_Y[(size_t)MROWS * DMODEL];

__device__ __forceinline__ float to_tf32(float x) {
    float r;
    asm("cvt.rna.tf32.f32 %0, %1;" : "=f"(r) : "f"(x));
    return r;
}

__device__ __forceinline__ void mma_m16n8k8(float c[4], const uint32_t a[4],
                                            const uint32_t b[2]) {
    asm volatile(
        "mma.sync.aligned.m16n8k8.row.col.f32.tf32.tf32.f32 "
        "{%0,%1,%2,%3}, {%4,%5,%6,%7}, {%8,%9}, {%0,%1,%2,%3};\n"
        : "+f"(c[0]), "+f"(c[1]), "+f"(c[2]), "+f"(c[3])
        : "r"(a[0]), "r"(a[1]), "r"(a[2]), "r"(a[3]),
          "r"(b[0]), "r"(b[1]));
}

// ---------------------------------------------------------------------------
// gemm_nt_v2: C[8192,1024] = A @ B^T + bias. CTA 128x128, 4 warps (2x2 of
// 64x64), BK=16, register-prefetch double buffer, 1 barrier per k-block.
// ---------------------------------------------------------------------------
__global__ __launch_bounds__(128, 2)
void gemm_nt_v2(const float* __restrict__ A, const float* __restrict__ B,
                float* __restrict__ C, const float* __restrict__ bias)
{
    __shared__ float As[2][128][20];
    __shared__ float Bs[2][128][20];

    const int m0 = blockIdx.y * 128;
    const int n0 = blockIdx.x * 128;
    const int tid  = threadIdx.x;
    const int lane = tid & 31;
    const int wid  = tid >> 5;
    const int g    = lane >> 2;
    const int tg   = lane & 3;
    const int wm0  = (wid >> 1) * 64;
    const int wn0  = (wid & 1) * 64;
    const int srow = tid >> 2;        // 0..31
    const int scol = (tid & 3) * 4;   // 0,4,8,12

    float acc[4][8][4];
#pragma unroll
    for (int i = 0; i < 4; i++)
#pragma unroll
        for (int j = 0; j < 8; j++)
#pragma unroll
            for (int r = 0; r < 4; r++) acc[i][j][r] = 0.0f;

    const float* Ap = A + (size_t)(m0 + srow) * DMODEL + scol;
    const float* Bp = B + (size_t)(n0 + srow) * DMODEL + scol;

    float4 ar[4], br[4];
#pragma unroll
    for (int q = 0; q < 4; q++) {
        ar[q] = *reinterpret_cast<const float4*>(Ap + (size_t)q * 32 * DMODEL);
        br[q] = *reinterpret_cast<const float4*>(Bp + (size_t)q * 32 * DMODEL);
    }
#pragma unroll
    for (int q = 0; q < 4; q++) {
        As[0][srow + 32 * q][scol + 0] = to_tf32(ar[q].x);
        As[0][srow + 32 * q][scol + 1] = to_tf32(ar[q].y);
        As[0][srow + 32 * q][scol + 2] = to_tf32(ar[q].z);
        As[0][srow + 32 * q][scol + 3] = to_tf32(ar[q].w);
        Bs[0][srow + 32 * q][scol + 0] = to_tf32(br[q].x);
        Bs[0][srow + 32 * q][scol + 1] = to_tf32(br[q].y);
        Bs[0][srow + 32 * q][scol + 2] = to_tf32(br[q].z);
        Bs[0][srow + 32 * q][scol + 3] = to_tf32(br[q].w);
    }
    __syncthreads();

    for (int kb = 0; kb < 64; kb++) {
        const int cur = kb & 1;
        if (kb < 63) {
            const float* An = Ap + (size_t)(kb + 1) * 16;
            const float* Bn = Bp + (size_t)(kb + 1) * 16;
#pragma unroll
            for (int q = 0; q < 4; q++) {
                ar[q] = *reinterpret_cast<const float4*>(An + (size_t)q * 32 * DMODEL);
                br[q] = *reinterpret_cast<const float4*>(Bn + (size_t)q * 32 * DMODEL);
            }
        }
#pragma unroll
        for (int kk = 0; kk < 16; kk += 8) {
            uint32_t af[4][4], bf[8][2];
#pragma unroll
            for (int mt = 0; mt < 4; mt++) {
                const int r = wm0 + mt * 16 + g;
                af[mt][0] = __float_as_uint(As[cur][r][kk + tg]);
                af[mt][1] = __float_as_uint(As[cur][r + 8][kk + tg]);
                af[mt][2] = __float_as_uint(As[cur][r][kk + tg + 4]);
                af[mt][3] = __float_as_uint(As[cur][r + 8][kk + tg + 4]);
            }
#pragma unroll
            for (int nt = 0; nt < 8; nt++) {
                const int c = wn0 + nt * 8 + g;
                bf[nt][0] = __float_as_uint(Bs[cur][c][kk + tg]);
                bf[nt][1] = __float_as_uint(Bs[cur][c][kk + tg + 4]);
            }
#pragma unroll
            for (int mt = 0; mt < 4; mt++)
#pragma unroll
                for (int nt = 0; nt < 8; nt++)
                    mma_m16n8k8(acc[mt][nt], af[mt], bf[nt]);
        }
        if (kb < 63) {
            const int nxt = cur ^ 1;
#pragma unroll
            for (int q = 0; q < 4; q++) {
                As[nxt][srow + 32 * q][scol + 0] = to_tf32(ar[q].x);
                As[nxt][srow + 32 * q][scol + 1] = to_tf32(ar[q].y);
                As[nxt][srow + 32 * q][scol + 2] = to_tf32(ar[q].z);
                As[nxt][srow + 32 * q][scol + 3] = to_tf32(ar[q].w);
                Bs[nxt][srow + 32 * q][scol + 0] = to_tf32(br[q].x);
                Bs[nxt][srow + 32 * q][scol + 1] = to_tf32(br[q].y);
                Bs[nxt][srow + 32 * q][scol + 2] = to_tf32(br[q].z);
                Bs[nxt][srow + 32 * q][scol + 3] = to_tf32(br[q].w);
            }
        }
        __syncthreads();
    }

#pragma unroll
    for (int mt = 0; mt < 4; mt++) {
#pragma unroll
        for (int nt = 0; nt < 8; nt++) {
            const int row0 = m0 + wm0 + mt * 16 + g;
            const int col  = n0 + wn0 + nt * 8 + 2 * tg;
            const float b0 = bias[col];
            const float b1 = bias[col + 1];
            *reinterpret_cast<float2*>(&C[(size_t)row0 * DMODEL + col]) =
                make_float2(acc[mt][nt][0] + b0, acc[mt][nt][1] + b1);
            *reinterpret_cast<float2*>(&C[(size_t)(row0 + 8) * DMODEL + col]) =
                make_float2(acc[mt][nt][2] + b0, acc[mt][nt][3] + b1);
        }
    }
}

// ---------------------------------------------------------------------------
// flash_attn_v2: grid (SEQ/128, 64), block 128 (4 warps, 32 q-rows each).
// Q in registers; K/V row-layout SMEM (conflict-free scalar frag reads);
// online softmax; P via warp-private SMEM rows.
// ---------------------------------------------------------------------------
__global__ __launch_bounds__(128, 2)
void flash_attn_v2(const float* __restrict__ Q,
                   const float* __restrict__ K,
                   const float* __restrict__ V,
                   float* __restrict__ Y)
{
    extern __shared__ float sm[];
    float* sP = sm + FP_P;
    float* sK = sm + FP_K;
    float* sV = sm + FP_V;

    const int z  = blockIdx.y;
    const int bn = z >> 4;
    const int h  = z & 15;

    const size_t rowbase = (size_t)bn * SEQ + (size_t)blockIdx.x * 128;
    const float* Qp = Q + rowbase * DMODEL + h * HDIM;
    const float* Kb = K + (size_t)bn * SEQ * DMODEL + h * HDIM;
    const float* Vb = V + (size_t)bn * SEQ * DMODEL + h * HDIM;
    float*       Yp = Y + rowbase * DMODEL + h * HDIM;

    const int tid  = threadIdx.x;
    const int lane = tid & 31;
    const int w    = tid >> 5;
    const int g    = lane >> 2;
    const int tg   = lane & 3;
    const int lr   = tid >> 4;         // 0..7
    const int lc   = (tid & 15) * 4;   // 0..60

    // stage Q (scaled, tf32) into sP, then lift to registers
#pragma unroll
    for (int r = 0; r < 16; r++) {
        const int row = r * 8 + lr;
        float4 v = *reinterpret_cast<const float4*>(&Qp[(size_t)row * DMODEL + lc]);
        sP[row * 68 + lc + 0] = to_tf32(v.x * ATT_SCALE);
        sP[row * 68 + lc + 1] = to_tf32(v.y * ATT_SCALE);
        sP[row * 68 + lc + 2] = to_tf32(v.z * ATT_SCALE);
        sP[row * 68 + lc + 3] = to_tf32(v.w * ATT_SCALE);
    }
    __syncthreads();

    uint32_t qreg[2][8][4];
#pragma unroll
    for (int mt = 0; mt < 2; mt++) {
        const int row = w * 32 + mt * 16 + g;
#pragma unroll
        for (int kk = 0; kk < 8; kk++) {
            qreg[mt][kk][0] = __float_as_uint(sP[row * 68 + kk * 8 + tg]);
            qreg[mt][kk][1] = __float_as_uint(sP[(row + 8) * 68 + kk * 8 + tg]);
            qreg[mt][kk][2] = __float_as_uint(sP[row * 68 + kk * 8 + tg + 4]);
            qreg[mt][kk][3] = __float_as_uint(sP[(row + 8) * 68 + kk * 8 + tg + 4]);
        }
    }

    float acc[2][8][4];
#pragma unroll
    for (int mt = 0; mt < 2; mt++)
#pragma unroll
        for (int nt = 0; nt < 8; nt++)
#pragma unroll
            for (int r = 0; r < 4; r++) acc[mt][nt][r] = 0.0f;
    float mrow[2][2] = {{-1e30f, -1e30f}, {-1e30f, -1e30f}};
    float lsum[2][2] = {{0.0f, 0.0f}, {0.0f, 0.0f}};

    for (int j = 0; j < SEQ / 64; j++) {
        __syncthreads();   // prev PV reads of sK/sV complete
#pragma unroll
        for (int r = 0; r < 8; r++) {
            const int row = r * 8 + lr;
            const size_t go = (size_t)(j * 64 + row) * DMODEL + lc;
            float4 kv = *reinterpret_cast<const float4*>(&Kb[go]);
            float4 vv = *reinterpret_cast<const float4*>(&Vb[go]);
            sK[row * 68 + lc + 0] = to_tf32(kv.x);
            sK[row * 68 + lc + 1] = to_tf32(kv.y);
            sK[row * 68 + lc + 2] = to_tf32(kv.z);
            sK[row * 68 + lc + 3] = to_tf32(kv.w);
            sV[row * 72 + lc + 0] = to_tf32(vv.x);
            sV[row * 72 + lc + 1] = to_tf32(vv.y);
            sV[row * 72 + lc + 2] = to_tf32(vv.z);
            sV[row * 72 + lc + 3] = to_tf32(vv.w);
        }
        __syncthreads();

        // S = Qs @ K^T  (per warp: 32 x 64)
        float s[2][8][4];
#pragma unroll
        for (int mt = 0; mt < 2; mt++)
#pragma unroll
            for (int nt = 0; nt < 8; nt++)
#pragma unroll
                for (int r = 0; r < 4; r++) s[mt][nt][r] = 0.0f;

#pragma unroll
        for (int kk = 0; kk < 8; kk++) {
            uint32_t bf[8][2];
#pragma unroll
            for (int nt = 0; nt < 8; nt++) {
                bf[nt][0] = __float_as_uint(sK[(nt * 8 + g) * 68 + kk * 8 + tg]);
                bf[nt][1] = __float_as_uint(sK[(nt * 8 + g) * 68 + kk * 8 + tg + 4]);
            }
#pragma unroll
            for (int nt = 0; nt < 8; nt++) {
                mma_m16n8k8(s[0][nt], qreg[0][kk], bf[nt]);
                mma_m16n8k8(s[1][nt], qreg[1][kk], bf[nt]);
            }
        }

        // online softmax + P store
#pragma unroll
        for (int mt = 0; mt < 2; mt++) {
            float mx0 = -1e30f, mx1 = -1e30f;
#pragma unroll
            for (int nt = 0; nt < 8; nt++) {
                mx0 = fmaxf(mx0, fmaxf(s[mt][nt][0], s[mt][nt][1]));
                mx1 = fmaxf(mx1, fmaxf(s[mt][nt][2], s[mt][nt][3]));
            }
            mx0 = fmaxf(mx0, __shfl_xor_sync(0xffffffffu, mx0, 1));
            mx0 = fmaxf(mx0, __shfl_xor_sync(0xffffffffu, mx0, 2));
            mx1 = fmaxf(mx1, __shfl_xor_sync(0xffffffffu, mx1, 1));
            mx1 = fmaxf(mx1, __shfl_xor_sync(0xffffffffu, mx1, 2));

            const float nm0 = fmaxf(mrow[mt][0], mx0);
            const float nm1 = fmaxf(mrow[mt][1], mx1);
            const float al0 = __expf(mrow[mt][0] - nm0);
            const float al1 = __expf(mrow[mt][1] - nm1);
            mrow[mt][0] = nm0; mrow[mt][1] = nm1;

            float rs0 = 0.0f, rs1 = 0.0f;
#pragma unroll
            for (int nt = 0; nt < 8; nt++) {
                s[mt][nt][0] = __expf(s[mt][nt][0] - nm0);
                s[mt][nt][1] = __expf(s[mt][nt][1] - nm0);
                s[mt][nt][2] = __expf(s[mt][nt][2] - nm1);
                s[mt][nt][3] = __expf(s[mt][nt][3] - nm1);
                rs0 += s[mt][nt][0] + s[mt][nt][1];
                rs1 += s[mt][nt][2] + s[mt][nt][3];
            }
            rs0 += __shfl_xor_sync(0xffffffffu, rs0, 1);
            rs0 += __shfl_xor_sync(0xffffffffu, rs0, 2);
            rs1 += __shfl_xor_sync(0xffffffffu, rs1, 1);
            rs1 += __shfl_xor_sync(0xffffffffu, rs1, 2);
            lsum[mt][0] = lsum[mt][0] * al0 + rs0;
            lsum[mt][1] = lsum[mt][1] * al1 + rs1;

#pragma unroll
            for (int nt = 0; nt < 8; nt++) {
                acc[mt][nt][0] *= al0; acc[mt][nt][1] *= al0;
                acc[mt][nt][2] *= al1; acc[mt][nt][3] *= al1;
            }
            const int row = w * 32 + mt * 16 + g;
#pragma unroll
            for (int nt = 0; nt < 8; nt++) {
                *reinterpret_cast<float2*>(&sP[row * 68 + nt * 8 + 2 * tg]) =
                    make_float2(to_tf32(s[mt][nt][0]), to_tf32(s[mt][nt][1]));
                *reinterpret_cast<float2*>(&sP[(row + 8) * 68 + nt * 8 + 2 * tg]) =
                    make_float2(to_tf32(s[mt][nt][2]), to_tf32(s[mt][nt][3]));
            }
        }
        __syncwarp();   // P rows are warp-private

        // O += P @ V
#pragma unroll
        for (int kk = 0; kk < 8; kk++) {
            uint32_t af[2][4], bf[8][2];
#pragma unroll
            for (int mt = 0; mt < 2; mt++) {
                const int row = w * 32 + mt * 16 + g;
                af[mt][0] = __float_as_uint(sP[row * 68 + kk * 8 + tg]);
                af[mt][1] = __float_as_uint(sP[(row + 8) * 68 + kk * 8 + tg]);
                af[mt][2] = __float_as_uint(sP[row * 68 + kk * 8 + tg + 4]);
                af[mt][3] = __float_as_uint(sP[(row + 8) * 68 + kk * 8 + tg + 4]);
            }
#pragma unroll
            for (int nt = 0; nt < 8; nt++) {
                bf[nt][0] = __float_as_uint(sV[(kk * 8 + tg) * 72 + nt * 8 + g]);
                bf[nt][1] = __float_as_uint(sV[(kk * 8 + tg + 4) * 72 + nt * 8 + g]);
            }
#pragma unroll
            for (int nt = 0; nt < 8; nt++) {
                mma_m16n8k8(acc[0][nt], af[0], bf[nt]);
                mma_m16n8k8(acc[1][nt], af[1], bf[nt]);
            }
        }
    }

#pragma unroll
    for (int mt = 0; mt < 2; mt++) {
        const float inv0 = 1.0f / lsum[mt][0];
        const float inv1 = 1.0f / lsum[mt][1];
        const int row = w * 32 + mt * 16 + g;
#pragma unroll
        for (int nt = 0; nt < 8; nt++) {
            *reinterpret_cast<float2*>(&Yp[(size_t)row * DMODEL + nt * 8 + 2 * tg]) =
                make_float2(acc[mt][nt][0] * inv0, acc[mt][nt][1] * inv0);
            *reinterpret_cast<float2*>(&Yp[(size_t)(row + 8) * DMODEL + nt * 8 + 2 * tg]) =
                make_float2(acc[mt][nt][2] * inv1, acc[mt][nt][3] * inv1);
        }
    }
}

// ---------------------------------------------------------------------------

extern "C" void kernel_launch(void* const* d_in, const int* in_sizes, int n_in,
                              void* d_out, int out_size)
{
    const float* x  = (const float*)d_in[0];
    const float* Wq = (const float*)d_in[1];
    const float* bq = (const float*)d_in[2];
    const float* Wk = (const float*)d_in[3];
    const float* bk = (const float*)d_in[4];
    const float* Wv = (const float*)d_in[5];
    const float* bv = (const float*)d_in[6];
    const float* Wp = (const float*)d_in[7];
    const float* bp = (const float*)d_in[8];
    float* out = (float*)d_out;

    float *Q, *Kp, *V, *Y;
    cudaGetSymbolAddress((void**)&Q,  g_Q);
    cudaGetSymbolAddress((void**)&Kp, g_K);
    cudaGetSymbolAddress((void**)&V,  g_V);
    cudaGetSymbolAddress((void**)&Y,  g_Y);

    constexpr int FLASH_SMEM_BYTES = FLASH_SMEM_FLOATS * 4;  // 70656
    cudaFuncSetAttribute(flash_attn_v2,
                         cudaFuncAttributeMaxDynamicSharedMemorySize,
                         FLASH_SMEM_BYTES);

    const dim3 blk(128);
    const dim3 gproj(DMODEL / 128, MROWS / 128);

    gemm_nt_v2<<<gproj, blk>>>(x, Wq, Q,  bq);
    gemm_nt_v2<<<gproj, blk>>>(x, Wk, Kp, bk);
    gemm_nt_v2<<<gproj, blk>>>(x, Wv, V,  bv);

    const dim3 gfa(SEQ / 128, BATCH * 16);
    flash_attn_v2<<<gfa, blk, FLASH_SMEM_BYTES>>>(Q, Kp, V, Y);

    gemm_nt_v2<<<gproj, blk>>>(Y, Wp, out, bp);
}